// round 15
// baseline (speedup 1.0000x reference)
#include <cuda_runtime.h>
#include <cuda_bf16.h>
#include <cstdint>

#define C_DIM 64
#define F_DIM 128
#define DEG 32
#define MAX_N 20000
#define MAX_E 640000
#define WARPS_PER_CTA 8
#define THREADS_PER_CTA (32 * WARPS_PER_CTA)
#define ROW_WORDS 40            // uint32 words per shared row (32 payload + 8 pad)
#define WARP_SM_WORDS (32 * ROW_WORDS + 32)   // s_cnt/s_es + s_src
#define WT_WORDS (F_DIM * ROW_WORDS)

// Scratch (device globals: no allocations allowed in kernel_launch)
__device__ unsigned g_wt[F_DIM * 32];   // bf16x2-packed, pair-permuted W^T rows
__device__ unsigned g_cursor[MAX_N];    // never reset; slot = old & 31
__device__ int2     g_pair[MAX_E];      // per-node {edge id, src*F_DIM}, DEG per node

__device__ __forceinline__ unsigned pack_bf2(float lo, float hi) {
    unsigned r;
    asm("cvt.rn.bf16x2.f32 %0, %1, %2;" : "=r"(r) : "f"(hi), "f"(lo));
    return r;
}

__device__ __forceinline__ float4 ldcs4(const float4* p) {
    float4 v;
    asm("ld.global.cs.v4.f32 {%0,%1,%2,%3}, [%4];"
        : "=f"(v.x), "=f"(v.y), "=f"(v.z), "=f"(v.w) : "l"(p));
    return v;
}
__device__ __forceinline__ int4 ldcs_i4(const int4* p) {
    int4 v;
    asm("ld.global.cs.v4.s32 {%0,%1,%2,%3}, [%4];"
        : "=r"(v.x), "=r"(v.y), "=r"(v.z), "=r"(v.w) : "l"(p));
    return v;
}

// ---------------------------------------------------------------------------
// scatter (4 edges/thread) + softmax in the last block.
// No cursor reset: slot = atomicAdd & 31 (exactly 32 increments per node per
// run; mod-32 of the old values is a permutation of 0..31; output is
// slot-order invariant).
// ---------------------------------------------------------------------------
__global__ void scatter_softmax_kernel(const int* __restrict__ dst,
                                       const int* __restrict__ src, int n_edges,
                                       const float* __restrict__ imp) {
    if (blockIdx.x == gridDim.x - 1) {
        int f = threadIdx.x;
        if (f < F_DIM) {
            float v[C_DIM];
            float m = -3.0e38f;
#pragma unroll
            for (int c = 0; c < C_DIM; c++) { v[c] = imp[c * F_DIM + f]; m = fmaxf(m, v[c]); }
            float s = 0.f;
#pragma unroll
            for (int c = 0; c < C_DIM; c++) { v[c] = expf(v[c] - m); s += v[c]; }
            float inv = 1.0f / s;
#pragma unroll
            for (int c = 0; c < C_DIM; c++) v[c] *= inv;
#pragma unroll
            for (int b = 0; b < 4; b++)
#pragma unroll
                for (int q = 0; q < 8; q++) {
                    int c0 = b * 16 + 2 * q;
                    g_wt[f * 32 + b * 8 + 2 * (q & 3) + (q >> 2)] =
                        pack_bf2(v[c0], v[c0 + 1]);
                }
        }
        return;
    }
    int base = (blockIdx.x * blockDim.x + threadIdx.x) * 4;
    if (base + 3 < n_edges) {
        int4 d4 = ldcs_i4(reinterpret_cast<const int4*>(dst + base));
        int4 s4 = ldcs_i4(reinterpret_cast<const int4*>(src + base));
#pragma unroll
        for (int i = 0; i < 4; i++) {
            int d = (i == 0) ? d4.x : (i == 1) ? d4.y : (i == 2) ? d4.z : d4.w;
            int s = (i == 0) ? s4.x : (i == 1) ? s4.y : (i == 2) ? s4.z : s4.w;
            unsigned slot = atomicAdd(&g_cursor[d], 1u) & (DEG - 1);
            long long pr = (long long)(unsigned)(base + i) |
                           ((long long)(s * F_DIM) << 32);
            asm volatile("st.global.cs.s64 [%0], %1;"
                         :: "l"(&g_pair[d * DEG + slot]), "l"(pr));
        }
    } else {
        for (int e = base; e < n_edges; e++) {
            int d = dst[e];
            unsigned slot = atomicAdd(&g_cursor[d], 1u) & (DEG - 1);
            long long pr = (long long)(unsigned)e |
                           ((long long)(src[e] * F_DIM) << 32);
            asm volatile("st.global.cs.s64 [%0], %1;"
                         :: "l"(&g_pair[d * DEG + slot]), "l"(pr));
        }
    }
}

// ---------------------------------------------------------------------------
// Main fused kernel: one warp = one node; bf16 m16n8k16 mma.
// R14 + emb prefetch: the 32 emb values per chunk are loaded into registers
// BEFORE the mma loop so the L2 round-trip hides under tensor work.
// ---------------------------------------------------------------------------
__global__ void __launch_bounds__(THREADS_PER_CTA, 2)
fogcn_main_kernel(const float* __restrict__ cnt,
                  const float* __restrict__ emb,
                  float*       __restrict__ out,
                  int n_nodes) {
    extern __shared__ unsigned smu[];
    unsigned* s_wt = smu;                                   // [128][40] words
    int wid  = threadIdx.x >> 5;
    int lane = threadIdx.x & 31;
    int tid  = threadIdx.x;
    unsigned* s_cnt = smu + WT_WORDS + wid * WARP_SM_WORDS; // [32][40] words
    int*      s_src = (int*)(s_cnt + 32 * ROW_WORDS);       // [32], pre-scaled

    // CTA-cooperative: stage packed W^T rows into shared (stride 40 words)
    {
        int row = tid >> 1, half = tid & 1;
        const uint4* g = reinterpret_cast<const uint4*>(g_wt + row * 32 + half * 16);
        uint4* d = reinterpret_cast<uint4*>(s_wt + row * ROW_WORDS + half * 16);
        d[0] = g[0]; d[1] = g[1]; d[2] = g[2]; d[3] = g[3];
    }
    __syncthreads();

    int node = blockIdx.x * WARPS_PER_CTA + wid;
    if (node >= n_nodes) return;

    int2 pr = g_pair[node * DEG + lane];        // coalesced 8B
    int e = pr.x;
    s_src[lane] = pr.y;                         // pre-scaled src row offset

    // --- cooperative coalesced cnt gather (streaming), bf16 pack + permute ---
    // odd rows: word columns XOR 2 -> STS banks disjoint from even rows
    {
        int half = lane >> 4;
        int par  = 2 * half;
        int u    = lane & 15;
        int boff = (u >> 2) * 8 + ((u & 1) * 4 + ((u >> 1) & 1));
        int p0 = boff ^ par;
        int p1 = (boff + 2) ^ par;
#pragma unroll
        for (int j = 0; j < 16; j++) {
            int row = 2 * j + half;
            int er  = __shfl_sync(0xffffffffu, e, row);
            float4 v = ldcs4(reinterpret_cast<const float4*>(cnt + (size_t)er * C_DIM) + u);
            unsigned* drow = s_cnt + row * ROW_WORDS;
            drow[p0] = pack_bf2(v.x, v.y);
            drow[p1] = pack_bf2(v.z, v.w);
        }
    }
    __syncwarp();

    int gid = lane >> 2;     // row-group 0..7
    int tig = lane & 3;      // thread-in-group 0..3
    int apar = 2 * (gid & 1);   // XOR parity for A-frag reads (row parity = gid&1)

    // --- hoist all A fragments (chunk-independent): 16 x LDS.64 = 32 regs ---
    uint2 af[4][2][2];       // [ks][mt][row-half]
#pragma unroll
    for (int ks = 0; ks < 4; ks++)
#pragma unroll
        for (int mt = 0; mt < 2; mt++)
#pragma unroll
            for (int h = 0; h < 2; h++)
                af[ks][mt][h] = *reinterpret_cast<const uint2*>(
                    s_cnt + (mt * 16 + gid + h * 8) * ROW_WORDS + ((ks * 8 + 2 * tig) ^ apar));
    __syncwarp();            // s_cnt now dead (A lives in regs) -> reuse as s_es

    float* s_es = reinterpret_cast<float*>(s_cnt);   // [32][40] floats (no swizzle)
    const float* embc = emb + lane;                  // lane owns chunk-column
    float* orow = out + (size_t)node * F_DIM;

#pragma unroll 1
    for (int cb = 0; cb < F_DIM; cb += 32) {
        const float* embb = embc + cb;

        // --- emb prefetch: issue all 32 L2 loads BEFORE the mma phase ---
        float embr[32];
#pragma unroll
        for (int rg = 0; rg < 8; rg++) {
            int4 s4 = reinterpret_cast<const int4*>(s_src)[rg];
            embr[4 * rg + 0] = embb[s4.x];
            embr[4 * rg + 1] = embb[s4.y];
            embr[4 * rg + 2] = embb[s4.z];
            embr[4 * rg + 3] = embb[s4.w];
        }

        float acc[2][4][4];
#pragma unroll
        for (int mt = 0; mt < 2; mt++)
#pragma unroll
            for (int t = 0; t < 4; t++)
#pragma unroll
                for (int i = 0; i < 4; i++) acc[mt][t][i] = 0.f;

#pragma unroll
        for (int ks = 0; ks < 4; ks++) {
            uint2 b2[4];
#pragma unroll
            for (int t = 0; t < 4; t++)
                b2[t] = *reinterpret_cast<const uint2*>(
                    s_wt + (cb + t * 8 + gid) * ROW_WORDS + ks * 8 + 2 * tig);
#pragma unroll
            for (int t = 0; t < 4; t++)
#pragma unroll
                for (int mt = 0; mt < 2; mt++)
                    asm volatile(
                        "mma.sync.aligned.m16n8k16.row.col.f32.bf16.bf16.f32 "
                        "{%0,%1,%2,%3}, {%4,%5,%6,%7}, {%8,%9}, {%0,%1,%2,%3};"
                        : "+f"(acc[mt][t][0]), "+f"(acc[mt][t][1]),
                          "+f"(acc[mt][t][2]), "+f"(acc[mt][t][3])
                        : "r"(af[ks][mt][0].x), "r"(af[ks][mt][1].x),
                          "r"(af[ks][mt][0].y), "r"(af[ks][mt][1].y),
                          "r"(b2[t].x), "r"(b2[t].y));
        }

        // --- write ES fragments to shared (stride 40, conflict-free STS.64) ---
        __syncwarp();
#pragma unroll
        for (int mt = 0; mt < 2; mt++)
#pragma unroll
            for (int t = 0; t < 4; t++) {
                int r = mt * 16 + gid;
                int c = t * 8 + tig * 2;
                *reinterpret_cast<float2*>(s_es + r * ROW_WORDS + c) =
                    make_float2(acc[mt][t][0], acc[mt][t][1]);
                *reinterpret_cast<float2*>(s_es + (r + 8) * ROW_WORDS + c) =
                    make_float2(acc[mt][t][2], acc[mt][t][3]);
            }
        __syncwarp();

        // --- reduction: lane = chunk-feature; es LDS + prefetched emb regs ---
        float num = 0.f, den = 0.f;
#pragma unroll
        for (int rg = 0; rg < 8; rg++) {
            float es0 = s_es[(4 * rg + 0) * ROW_WORDS + lane];
            float es1 = s_es[(4 * rg + 1) * ROW_WORDS + lane];
            float es2 = s_es[(4 * rg + 2) * ROW_WORDS + lane];
            float es3 = s_es[(4 * rg + 3) * ROW_WORDS + lane];
            num = fmaf(es0, embr[4 * rg + 0], num);
            num = fmaf(es1, embr[4 * rg + 1], num);
            num = fmaf(es2, embr[4 * rg + 2], num);
            num = fmaf(es3, embr[4 * rg + 3], num);
            den += (es0 + es1) + (es2 + es3);
        }
        {
            float o = __fdividef(num, den);
            asm volatile("st.global.cs.f32 [%0], %1;" :: "l"(orow + cb + lane), "f"(o));
        }
        __syncwarp();   // protect s_es before next chunk's stores
    }
}

// ---------------------------------------------------------------------------
extern "C" void kernel_launch(void* const* d_in, const int* in_sizes, int n_in,
                              void* d_out, int out_size) {
    const float* cnt = (const float*)d_in[0];
    const float* emb = (const float*)d_in[1];
    const float* imp = (const float*)d_in[2];
    const int*   src = (const int*)d_in[3];
    const int*   dst = (const int*)d_in[4];
    float*       out = (float*)d_out;

    int n_edges = in_sizes[3];
    int n_nodes = in_sizes[1] / F_DIM;
    if (n_edges > MAX_E) n_edges = MAX_E;
    if (n_nodes > MAX_N) n_nodes = MAX_N;

    // scatter (4 edges/thread) + softmax fused; no cursor reset needed
    int sblocks = ((n_edges + 3) / 4 + 255) / 256;
    scatter_softmax_kernel<<<sblocks + 1, 256>>>(dst, src, n_edges, imp);

    int smem_bytes = (WT_WORDS + WARPS_PER_CTA * WARP_SM_WORDS) * (int)sizeof(unsigned);
    cudaFuncSetAttribute(fogcn_main_kernel,
                         cudaFuncAttributeMaxDynamicSharedMemorySize, smem_bytes);

    int nblocks = (n_nodes + WARPS_PER_CTA - 1) / WARPS_PER_CTA;
    fogcn_main_kernel<<<nblocks, THREADS_PER_CTA, smem_bytes>>>(cnt, emb, out, n_nodes);
}